// round 4
// baseline (speedup 1.0000x reference)
#include <cuda_runtime.h>

// Conv as implicit GEMM:
//   A = W  [256 x 1152]   (row-major: oc, ic*9 + r*3 + s  — matches (O,I,3,3) layout)
//   B = im2col(x) [1152 x 49284], B[k][n] = x[c][oh+r][ow+s]
//   O = A @ B  [256 x 49284]
#define CIN   128
#define HIN   224
#define WIN   224
#define COUT  256
#define HO    222
#define WO    222
#define NPIX  (HO * WO)      // 49284
#define KDIM  (CIN * 9)      // 1152

#define BM 128
#define BN 128
#define BK 8
#define NTHREADS 256

__global__ __launch_bounds__(NTHREADS, 2)
void conv_igemm_kernel(const float* __restrict__ X,
                       const float* __restrict__ Wt,
                       float* __restrict__ O)
{
    __shared__ float As[BK][BM];
    __shared__ float Bs[BK][BN];
    __shared__ int   pbase[BN];   // per-pixel input base offset (oh*224 + ow)

    const int tid = threadIdx.x;
    const int n0  = blockIdx.x * BN;   // pixel tile origin
    const int m0  = blockIdx.y * BM;   // out-channel tile origin

    // Precompute the 128 pixel base offsets once; reused for all 144 K-iters.
    if (tid < BN) {
        int n = n0 + tid;
        if (n >= NPIX) n = NPIX - 1;      // clamp: loads stay in-bounds, stores guarded
        int oh = n / WO;
        int ow = n - oh * WO;
        pbase[tid] = oh * WIN + ow;
    }

    // A-tile load mapping: 128 rows x 8 cols, float4 per thread
    const int arow = tid >> 1;
    const int acol = (tid & 1) * 4;
    // B-tile load mapping: 8 rows (k) x 128 cols (n), 4 scalar loads per thread
    const int bkk = tid >> 5;
    const int bj  = tid & 31;

    // 8x8 microkernel mapping
    const int ty = tid >> 4;   // 0..15 -> oc group
    const int tx = tid & 15;   // 0..15 -> pixel group

    float acc[8][8];
    #pragma unroll
    for (int i = 0; i < 8; i++)
        #pragma unroll
        for (int j = 0; j < 8; j++) acc[i][j] = 0.0f;

    __syncthreads();   // pbase ready

    for (int k0 = 0; k0 < KDIM; k0 += BK) {
        // ---- load A tile (coalesced float4, stored transposed) ----
        float4 av = *reinterpret_cast<const float4*>(
            &Wt[(m0 + arow) * KDIM + k0 + acol]);
        As[acol + 0][arow] = av.x;
        As[acol + 1][arow] = av.y;
        As[acol + 2][arow] = av.z;
        As[acol + 3][arow] = av.w;

        // ---- load B tile (im2col on the fly) ----
        {
            int k  = k0 + bkk;
            int c  = k / 9;
            int rs = k - 9 * c;
            int r  = rs / 3;
            int s  = rs - 3 * r;
            const float* xp = X + c * (HIN * WIN) + r * WIN + s;
            #pragma unroll
            for (int it = 0; it < 4; it++) {
                int j = bj + it * 32;
                Bs[bkk][j] = xp[pbase[j]];
            }
        }
        __syncthreads();

        // ---- 8x8x8 FFMA microkernel ----
        #pragma unroll
        for (int kk = 0; kk < BK; kk++) {
            float a[8], b[8];
            *reinterpret_cast<float4*>(&a[0]) =
                *reinterpret_cast<const float4*>(&As[kk][ty * 8]);
            *reinterpret_cast<float4*>(&a[4]) =
                *reinterpret_cast<const float4*>(&As[kk][ty * 8 + 4]);
            *reinterpret_cast<float4*>(&b[0]) =
                *reinterpret_cast<const float4*>(&Bs[kk][tx * 8]);
            *reinterpret_cast<float4*>(&b[4]) =
                *reinterpret_cast<const float4*>(&Bs[kk][tx * 8 + 4]);
            #pragma unroll
            for (int i = 0; i < 8; i++)
                #pragma unroll
                for (int j = 0; j < 8; j++)
                    acc[i][j] += a[i] * b[j];
        }
        __syncthreads();
    }

    // ---- epilogue ----
    const int nbase = n0 + tx * 8;
    #pragma unroll
    for (int i = 0; i < 8; i++) {
        int oc = m0 + ty * 8 + i;
        float* orow = O + (size_t)oc * NPIX + nbase;
        if (nbase + 7 < NPIX) {
            *reinterpret_cast<float4*>(orow) =
                make_float4(acc[i][0], acc[i][1], acc[i][2], acc[i][3]);
            *reinterpret_cast<float4*>(orow + 4) =
                make_float4(acc[i][4], acc[i][5], acc[i][6], acc[i][7]);
        } else {
            #pragma unroll
            for (int j = 0; j < 8; j++)
                if (nbase + j < NPIX) orow[j] = acc[i][j];
        }
    }
}

extern "C" void kernel_launch(void* const* d_in, const int* in_sizes, int n_in,
                              void* d_out, int out_size)
{
    const float* X  = (const float*)d_in[0];   // (128, 224, 224) fp32
    const float* Wt = (const float*)d_in[1];   // (256, 128, 3, 3) fp32
    float* O        = (float*)d_out;           // (256, 222, 222) fp32

    dim3 grid((NPIX + BN - 1) / BN, COUT / BM);   // 386 x 2
    conv_igemm_kernel<<<grid, NTHREADS>>>(X, Wt, O);
}

// round 9
// speedup vs baseline: 2.8850x; 2.8850x over previous
#include <cuda_runtime.h>
#include <cuda_bf16.h>
#include <cstdint>

// ---------------- problem dims ----------------
#define CIN   128
#define HIN   224
#define WIN   224
#define COUT  256
#define HO    222
#define WO    222
#define NPIX  (HO * WO)       // 49284
#define KDIM  (CIN * 9)       // 1152

// ---------------- tiling ----------------
#define BM   128
#define BN   128
#define BK   64               // fp32 K per smem stage = 4 mma K-steps of 16
#define KSTAGES (KDIM / BK)   // 18
#define NTH  256              // 8 warps: 2 (m) x 4 (n), warp tile 64x32

// ---------------- smem layout ----------------
// per buffer: AHI, ALO, BHI, BLO — each 128 rows x 128B (SW128-swizzled), 16KB
#define TILE_B   (128 * 128)
#define OFF_AHI  0
#define OFF_ALO  (1 * TILE_B)
#define OFF_BHI  (2 * TILE_B)
#define OFF_BLO  (3 * TILE_B)
#define BUF_B    (4 * TILE_B)            // 65536 per buffer
#define OFF_KOFF (2 * BUF_B)             // 131072
#define SMEM_TOTAL (OFF_KOFF + KDIM * 4) // 135680

__device__ __forceinline__ uint32_t smem_u32(const void* p) {
    uint32_t a;
    asm("{ .reg .u64 t; cvta.to.shared.u64 t, %1; cvt.u32.u64 %0, t; }" : "=r"(a) : "l"(p));
    return a;
}

__device__ __forceinline__ void ldsm_x4(uint32_t* r, uint32_t addr) {
    asm volatile("ldmatrix.sync.aligned.m8n8.x4.shared.b16 {%0,%1,%2,%3}, [%4];"
                 : "=r"(r[0]), "=r"(r[1]), "=r"(r[2]), "=r"(r[3]) : "r"(addr));
}

__device__ __forceinline__ void mma_bf16(float* d, const uint32_t* a, const uint32_t* b) {
    asm volatile(
        "mma.sync.aligned.m16n8k16.row.col.f32.bf16.bf16.f32 "
        "{%0,%1,%2,%3}, {%4,%5,%6,%7}, {%8,%9}, {%0,%1,%2,%3};"
        : "+f"(d[0]), "+f"(d[1]), "+f"(d[2]), "+f"(d[3])
        : "r"(a[0]), "r"(a[1]), "r"(a[2]), "r"(a[3]), "r"(b[0]), "r"(b[1]));
}

// split 8 consecutive-k fp32 -> one 16B chunk of bf16 hi + one of lo
__device__ __forceinline__ void split8(const float* f, uint4& h, uint4& l) {
    uint32_t hb[4], lb[4];
    #pragma unroll
    for (int q = 0; q < 4; q++) {
        __nv_bfloat162 hp = __floats2bfloat162_rn(f[2*q], f[2*q+1]);
        uint32_t b = *reinterpret_cast<uint32_t*>(&hp);
        float fx = __uint_as_float(b << 16);
        float fy = __uint_as_float(b & 0xffff0000u);
        __nv_bfloat162 lp = __floats2bfloat162_rn(f[2*q] - fx, f[2*q+1] - fy);
        hb[q] = b;
        lb[q] = *reinterpret_cast<uint32_t*>(&lp);
    }
    h = make_uint4(hb[0], hb[1], hb[2], hb[3]);
    l = make_uint4(lb[0], lb[1], lb[2], lb[3]);
}

__global__ __launch_bounds__(NTH, 1)
void conv_mma_kernel(const float* __restrict__ X,
                     const float* __restrict__ Wt,
                     float* __restrict__ O)
{
    extern __shared__ __align__(1024) char smem[];
    const int tid  = threadIdx.x;
    const int wid  = tid >> 5;
    const int lane = tid & 31;
    const uint32_t sb = smem_u32(smem);

    const int n0 = blockIdx.x * BN;
    const int m0 = blockIdx.y * BM;

    // ---- im2col offset table ----
    int* koff_w = (int*)(smem + OFF_KOFF);
    for (int i = tid; i < KDIM; i += NTH) {
        int c  = i / 9;
        int rs = i - 9 * c;
        int r  = rs / 3;
        koff_w[i] = c * (HIN * WIN) + r * WIN + (rs - 3 * r);
    }
    __syncthreads();
    const int* koff = (const int*)(smem + OFF_KOFF);

    // ---- per-thread load mapping (A row / B pixel + k-half) ----
    const int lrow  = tid >> 1;            // 0..127: A row == B pixel index in tile
    const int khalf = (tid & 1) * 32;      // first or second 32 k of the stage
    const int cb    = (tid & 1) * 4;       // base 16B-chunk index

    int np = n0 + lrow;
    if (np >= NPIX) np = NPIX - 1;         // clamp: loads in-bounds, stores guarded
    const float* Xp = X + np + 2 * (np / WO);
    const float* Ap = Wt + (size_t)(m0 + lrow) * KDIM + khalf;

    // ---- warp tile mapping ----
    const int wm = wid & 1;                // 0..1  (64-row m slab)
    const int wn = wid >> 1;               // 0..3  (32-col n slab)

    // ldmatrix lane address precompute (SW128: chunk ^= row&7; row&7 == lane&7)
    const uint32_t aswz   = (uint32_t)(lane & 7);
    const int      g      = lane >> 3;
    const uint32_t a_coff = (uint32_t)(g >> 1);
    const uint32_t b_coff = (uint32_t)(g & 1);
    uint32_t arowb[4], bnb[2];
    #pragma unroll
    for (int mf = 0; mf < 4; mf++)
        arowb[mf] = (uint32_t)((wm * 64 + mf * 16 + ((g & 1) << 3) + (lane & 7)) << 7);
    #pragma unroll
    for (int nf2 = 0; nf2 < 2; nf2++)
        bnb[nf2] = (uint32_t)((wn * 32 + nf2 * 16 + ((g >> 1) << 3) + (lane & 7)) << 7);

    float acc[4][4][4];
    #pragma unroll
    for (int i = 0; i < 4; i++)
        #pragma unroll
        for (int j = 0; j < 4; j++)
            #pragma unroll
            for (int q = 0; q < 4; q++) acc[i][j][q] = 0.0f;

    // ---- preload stage 0 into buffer 0 ----
    {
        char* bufp = smem;  // buffer 0
        #pragma unroll
        for (int j2 = 0; j2 < 4; j2++) {
            float fa[8];
            *(float4*)&fa[0] = *(const float4*)(Ap + j2 * 8);
            *(float4*)&fa[4] = *(const float4*)(Ap + j2 * 8 + 4);
            uint4 h, l;
            split8(fa, h, l);
            const uint32_t off = (uint32_t)(lrow * 128) + ((uint32_t)((cb + j2) ^ (lrow & 7)) << 4);
            *(uint4*)(bufp + OFF_AHI + off) = h;
            *(uint4*)(bufp + OFF_ALO + off) = l;
        }
        #pragma unroll
        for (int j2 = 0; j2 < 4; j2++) {
            float fb[8];
            #pragma unroll
            for (int jj = 0; jj < 8; jj++) fb[jj] = Xp[koff[khalf + j2 * 8 + jj]];
            uint4 h, l;
            split8(fb, h, l);
            const uint32_t off = (uint32_t)(lrow * 128) + ((uint32_t)((cb + j2) ^ (lrow & 7)) << 4);
            *(uint4*)(bufp + OFF_BHI + off) = h;
            *(uint4*)(bufp + OFF_BLO + off) = l;
        }
    }
    __syncthreads();

    // ---- main loop ----
    for (int s = 0; s < KSTAGES; s++) {
        const int buf = s & 1;
        const bool more = (s + 1 < KSTAGES);

        // prefetch next stage into registers (LDG issue before compute)
        float apf[32], bpf[32];
        if (more) {
            const int kn = (s + 1) * BK;
            #pragma unroll
            for (int j = 0; j < 8; j++)
                *(float4*)&apf[j * 4] = *(const float4*)(Ap + kn + j * 4);
            #pragma unroll
            for (int j = 0; j < 32; j++)
                bpf[j] = Xp[koff[kn + khalf + j]];
        }

        // ---- compute on current buffer ----
        {
            const uint32_t ahiB = sb + buf * BUF_B + OFF_AHI;
            const uint32_t aloB = sb + buf * BUF_B + OFF_ALO;
            const uint32_t bhiB = sb + buf * BUF_B + OFF_BHI;
            const uint32_t bloB = sb + buf * BUF_B + OFF_BLO;

            #pragma unroll
            for (int ks = 0; ks < 4; ks++) {
                const uint32_t kc = (uint32_t)(2 * ks);
                const uint32_t aoff = ((kc + a_coff) ^ aswz) << 4;
                const uint32_t boff = ((kc + b_coff) ^ aswz) << 4;

                uint32_t ah[4][4], al[4][4], bh[2][4], bl[2][4];
                #pragma unroll
                for (int mf = 0; mf < 4; mf++) {
                    ldsm_x4(ah[mf], ahiB + arowb[mf] + aoff);
                    ldsm_x4(al[mf], aloB + arowb[mf] + aoff);
                }
                #pragma unroll
                for (int nf2 = 0; nf2 < 2; nf2++) {
                    ldsm_x4(bh[nf2], bhiB + bnb[nf2] + boff);
                    ldsm_x4(bl[nf2], bloB + bnb[nf2] + boff);
                }
                #pragma unroll
                for (int mf = 0; mf < 4; mf++)
                    #pragma unroll
                    for (int nf = 0; nf < 4; nf++) {
                        const uint32_t* bhp = &bh[nf >> 1][(nf & 1) * 2];
                        const uint32_t* blp = &bl[nf >> 1][(nf & 1) * 2];
                        mma_bf16(acc[mf][nf], ah[mf], bhp);   // hi*hi
                        mma_bf16(acc[mf][nf], ah[mf], blp);   // hi*lo
                        mma_bf16(acc[mf][nf], al[mf], bhp);   // lo*hi
                    }
            }
        }

        // ---- convert + store next stage into other buffer ----
        if (more) {
            char* bufp = smem + (buf ^ 1) * BUF_B;
            #pragma unroll
            for (int j2 = 0; j2 < 4; j2++) {
                uint4 h, l;
                split8(&apf[j2 * 8], h, l);
                const uint32_t off = (uint32_t)(lrow * 128) + ((uint32_t)((cb + j2) ^ (lrow & 7)) << 4);
                *(uint4*)(bufp + OFF_AHI + off) = h;
                *(uint4*)(bufp + OFF_ALO + off) = l;
            }
            #pragma unroll
            for (int j2 = 0; j2 < 4; j2++) {
                uint4 h, l;
                split8(&bpf[j2 * 8], h, l);
                const uint32_t off = (uint32_t)(lrow * 128) + ((uint32_t)((cb + j2) ^ (lrow & 7)) << 4);
                *(uint4*)(bufp + OFF_BHI + off) = h;
                *(uint4*)(bufp + OFF_BLO + off) = l;
            }
        }
        __syncthreads();
    }

    // ---- epilogue: register accumulators -> global ----
    const bool full = (n0 + BN <= NPIX);
    #pragma unroll
    for (int mf = 0; mf < 4; mf++) {
        const int r0 = m0 + wm * 64 + mf * 16 + (lane >> 2);
        #pragma unroll
        for (int nf = 0; nf < 4; nf++) {
            const int c = n0 + wn * 32 + nf * 8 + (lane & 3) * 2;
            float* p0 = O + (size_t)r0 * NPIX + c;
            float* p1 = p0 + 8 * NPIX;   // row r0+8
            if (full) {
                *(float2*)p0 = make_float2(acc[mf][nf][0], acc[mf][nf][1]);
                *(float2*)p1 = make_float2(acc[mf][nf][2], acc[mf][nf][3]);
            } else {
                if (c < NPIX)     { p0[0] = acc[mf][nf][0]; p1[0] = acc[mf][nf][2]; }
                if (c + 1 < NPIX) { p0[1] = acc[mf][nf][1]; p1[1] = acc[mf][nf][3]; }
            }
        }
    }
}

extern "C" void kernel_launch(void* const* d_in, const int* in_sizes, int n_in,
                              void* d_out, int out_size)
{
    const float* X  = (const float*)d_in[0];   // (128, 224, 224) fp32
    const float* Wt = (const float*)d_in[1];   // (256, 128, 3, 3) fp32
    float* O        = (float*)d_out;           // (256, 222, 222) fp32

    cudaFuncSetAttribute(conv_mma_kernel,
                         cudaFuncAttributeMaxDynamicSharedMemorySize, SMEM_TOTAL);

    dim3 grid((NPIX + BN - 1) / BN, COUT / BM);   // 386 x 2
    conv_mma_kernel<<<grid, NTH, SMEM_TOTAL>>>(X, Wt, O);
}

// round 12
// speedup vs baseline: 3.6857x; 1.2776x over previous
#include <cuda_runtime.h>
#include <cuda_fp16.h>
#include <cstdint>

// ---------------- problem dims ----------------
#define CIN   128
#define HIN   224
#define WIN   224
#define COUT  256
#define HO    222
#define WO    222
#define NPIX  (HO * WO)       // 49284
#define KDIM  (CIN * 9)       // 1152

// ---------------- tiling ----------------
#define BM   128
#define BN   256
#define BK   64               // fp32 K per smem stage = 4 mma K-steps of 16
#define KSTAGES (KDIM / BK)   // 18
#define NTH  256              // 8 warps: 2 (m) x 4 (n), warp tile 64x64

// ---------------- smem layout ----------------
// per buffer: AHI (128x128B), ALO (128x128B), BHI (256x128B)  == 64KB
#define A_TILE_B (128 * 128)
#define B_TILE_B (256 * 128)
#define OFF_AHI  0
#define OFF_ALO  (A_TILE_B)
#define OFF_BHI  (2 * A_TILE_B)
#define BUF_B    (2 * A_TILE_B + B_TILE_B)      // 65536
#define OFF_KOFF (2 * BUF_B)                    // 131072
#define SMEM_TOTAL (OFF_KOFF + KDIM * 4)        // 135680

__device__ __forceinline__ uint32_t smem_u32(const void* p) {
    uint32_t a;
    asm("{ .reg .u64 t; cvta.to.shared.u64 t, %1; cvt.u32.u64 %0, t; }" : "=r"(a) : "l"(p));
    return a;
}

__device__ __forceinline__ void ldsm_x4(uint32_t* r, uint32_t addr) {
    asm volatile("ldmatrix.sync.aligned.m8n8.x4.shared.b16 {%0,%1,%2,%3}, [%4];"
                 : "=r"(r[0]), "=r"(r[1]), "=r"(r[2]), "=r"(r[3]) : "r"(addr));
}

__device__ __forceinline__ void mma_f16(float* d, const uint32_t* a, const uint32_t* b) {
    asm volatile(
        "mma.sync.aligned.m16n8k16.row.col.f32.f16.f16.f32 "
        "{%0,%1,%2,%3}, {%4,%5,%6,%7}, {%8,%9}, {%0,%1,%2,%3};"
        : "+f"(d[0]), "+f"(d[1]), "+f"(d[2]), "+f"(d[3])
        : "r"(a[0]), "r"(a[1]), "r"(a[2]), "r"(a[3]), "r"(b[0]), "r"(b[1]));
}

// split 8 consecutive-k fp32 -> fp16 hi chunk + fp16 lo chunk (A only)
__device__ __forceinline__ void split8(const float* f, uint4& h, uint4& l) {
    uint32_t hb[4], lb[4];
    #pragma unroll
    for (int q = 0; q < 4; q++) {
        __half2 hp = __floats2half2_rn(f[2*q], f[2*q+1]);
        float2 hf = __half22float2(hp);
        __half2 lp = __floats2half2_rn(f[2*q] - hf.x, f[2*q+1] - hf.y);
        hb[q] = *reinterpret_cast<uint32_t*>(&hp);
        lb[q] = *reinterpret_cast<uint32_t*>(&lp);
    }
    h = make_uint4(hb[0], hb[1], hb[2], hb[3]);
    l = make_uint4(lb[0], lb[1], lb[2], lb[3]);
}

// round 8 consecutive-k fp32 -> one fp16 chunk (B)
__device__ __forceinline__ uint4 pack8(const float* f) {
    uint32_t hb[4];
    #pragma unroll
    for (int q = 0; q < 4; q++) {
        __half2 hp = __floats2half2_rn(f[2*q], f[2*q+1]);
        hb[q] = *reinterpret_cast<uint32_t*>(&hp);
    }
    return make_uint4(hb[0], hb[1], hb[2], hb[3]);
}

__global__ __launch_bounds__(NTH, 1)
void conv_mma2_kernel(const float* __restrict__ X,
                      const float* __restrict__ Wt,
                      float* __restrict__ O)
{
    extern __shared__ __align__(1024) char smem[];
    const int tid  = threadIdx.x;
    const int wid  = tid >> 5;
    const int lane = tid & 31;
    const uint32_t sb = smem_u32(smem);

    const int n0 = blockIdx.x * BN;
    const int m0 = blockIdx.y * BM;

    // ---- im2col offset table ----
    int* koff_w = (int*)(smem + OFF_KOFF);
    for (int i = tid; i < KDIM; i += NTH) {
        int c  = i / 9;
        int rs = i - 9 * c;
        int r  = rs / 3;
        koff_w[i] = c * (HIN * WIN) + r * WIN + (rs - 3 * r);
    }
    __syncthreads();
    const int* koff = (const int*)(smem + OFF_KOFF);

    // ---- B load mapping: one pixel row per thread, all 64 k of the stage ----
    int np = n0 + tid;
    if (np >= NPIX) np = NPIX - 1;         // clamp: loads in-bounds, stores guarded
    const float* Xp = X + np + 2 * (np / WO);
    const uint32_t brow  = (uint32_t)(tid * 128);
    const uint32_t bswz  = (uint32_t)(tid & 7);

    // ---- A load mapping: row = tid>>1, k-half = (tid&1)*32 ----
    const int lrow  = tid >> 1;
    const int khalf = (tid & 1) * 32;
    const int cbA   = (tid & 1) * 4;
    const float* Ap = Wt + (size_t)(m0 + lrow) * KDIM + khalf;
    const uint32_t arow = (uint32_t)(lrow * 128);
    const uint32_t aswzr = (uint32_t)(lrow & 7);

    // ---- warp tile mapping: 64 (m) x 64 (n) ----
    const int wm = wid & 1;
    const int wn = wid >> 1;

    const uint32_t aswz   = (uint32_t)(lane & 7);
    const int      g      = lane >> 3;
    const uint32_t a_coff = (uint32_t)(g >> 1);
    const uint32_t b_coff = (uint32_t)(g & 1);
    uint32_t arowb[4], bnb[4];
    #pragma unroll
    for (int mf = 0; mf < 4; mf++)
        arowb[mf] = (uint32_t)((wm * 64 + mf * 16 + ((g & 1) << 3) + (lane & 7)) << 7);
    #pragma unroll
    for (int nf2 = 0; nf2 < 4; nf2++)
        bnb[nf2] = (uint32_t)((wn * 64 + nf2 * 16 + ((g >> 1) << 3) + (lane & 7)) << 7);

    float acc[4][8][4];
    #pragma unroll
    for (int i = 0; i < 4; i++)
        #pragma unroll
        for (int j = 0; j < 8; j++)
            #pragma unroll
            for (int q = 0; q < 4; q++) acc[i][j][q] = 0.0f;

    // ---- preload stage 0 into buffer 0 ----
    {
        char* bufp = smem;
        // A: 32 k -> hi/lo, 4 chunks each
        #pragma unroll
        for (int j2 = 0; j2 < 4; j2++) {
            float fa[8];
            *(float4*)&fa[0] = *(const float4*)(Ap + j2 * 8);
            *(float4*)&fa[4] = *(const float4*)(Ap + j2 * 8 + 4);
            uint4 h, l;
            split8(fa, h, l);
            const uint32_t off = arow + ((((uint32_t)(cbA + j2)) ^ aswzr) << 4);
            *(uint4*)(bufp + OFF_AHI + off) = h;
            *(uint4*)(bufp + OFF_ALO + off) = l;
        }
        // B: 64 k -> 8 chunks
        #pragma unroll
        for (int c = 0; c < 8; c++) {
            float fb[8];
            #pragma unroll
            for (int jj = 0; jj < 8; jj++) fb[jj] = Xp[koff[c * 8 + jj]];
            const uint32_t off = brow + ((((uint32_t)c) ^ bswz) << 4);
            *(uint4*)(bufp + OFF_BHI + off) = pack8(fb);
        }
    }
    __syncthreads();

    // ---- main loop ----
    for (int s = 0; s < KSTAGES; s++) {
        const int buf = s & 1;
        const bool more = (s + 1 < KSTAGES);
        const int kn = (s + 1) * BK;

        // prefetch first half of next B stage into registers
        float bpf[32];
        if (more) {
            #pragma unroll
            for (int j = 0; j < 32; j++) bpf[j] = Xp[koff[kn + j]];
        }

        // ---- compute on current buffer ----
        {
            const uint32_t ahiB = sb + buf * BUF_B + OFF_AHI;
            const uint32_t aloB = sb + buf * BUF_B + OFF_ALO;
            const uint32_t bhiB = sb + buf * BUF_B + OFF_BHI;

            #pragma unroll
            for (int ks = 0; ks < 4; ks++) {
                const uint32_t kc = (uint32_t)(2 * ks);
                const uint32_t aoff = ((kc + a_coff) ^ aswz) << 4;
                const uint32_t boff = ((kc + b_coff) ^ aswz) << 4;

                uint32_t ah[4][4], al[4][4], bh[4][4];
                #pragma unroll
                for (int mf = 0; mf < 4; mf++) {
                    ldsm_x4(ah[mf], ahiB + arowb[mf] + aoff);
                    ldsm_x4(al[mf], aloB + arowb[mf] + aoff);
                }
                #pragma unroll
                for (int nf2 = 0; nf2 < 4; nf2++)
                    ldsm_x4(bh[nf2], bhiB + bnb[nf2] + boff);

                #pragma unroll
                for (int mf = 0; mf < 4; mf++)
                    #pragma unroll
                    for (int nf = 0; nf < 8; nf++) {
                        const uint32_t* bp = &bh[nf >> 1][(nf & 1) * 2];
                        mma_f16(acc[mf][nf], ah[mf], bp);   // Ah * Bh
                        mma_f16(acc[mf][nf], al[mf], bp);   // Al * Bh
                    }
            }
        }

        // ---- fill other buffer for next stage ----
        if (more) {
            char* bufp = smem + (buf ^ 1) * BUF_B;
            // B first half from prefetch regs
            #pragma unroll
            for (int c = 0; c < 4; c++) {
                const uint32_t off = brow + ((((uint32_t)c) ^ bswz) << 4);
                *(uint4*)(bufp + OFF_BHI + off) = pack8(&bpf[c * 8]);
            }
            // B second half direct
            #pragma unroll
            for (int c = 4; c < 8; c++) {
                float fb[8];
                #pragma unroll
                for (int jj = 0; jj < 8; jj++) fb[jj] = Xp[koff[kn + c * 8 + jj]];
                const uint32_t off = brow + ((((uint32_t)c) ^ bswz) << 4);
                *(uint4*)(bufp + OFF_BHI + off) = pack8(fb);
            }
            // A
            #pragma unroll
            for (int j2 = 0; j2 < 4; j2++) {
                float fa[8];
                *(float4*)&fa[0] = *(const float4*)(Ap + kn + j2 * 8);
                *(float4*)&fa[4] = *(const float4*)(Ap + kn + j2 * 8 + 4);
                uint4 h, l;
                split8(fa, h, l);
                const uint32_t off = arow + ((((uint32_t)(cbA + j2)) ^ aswzr) << 4);
                *(uint4*)(bufp + OFF_AHI + off) = h;
                *(uint4*)(bufp + OFF_ALO + off) = l;
            }
        }
        __syncthreads();
    }

    // ---- epilogue ----
    const bool full = (n0 + BN <= NPIX);
    #pragma unroll
    for (int mf = 0; mf < 4; mf++) {
        const int r0 = m0 + wm * 64 + mf * 16 + (lane >> 2);
        #pragma unroll
        for (int nf = 0; nf < 8; nf++) {
            const int c = n0 + wn * 64 + nf * 8 + (lane & 3) * 2;
            float* p0 = O + (size_t)r0 * NPIX + c;
            float* p1 = p0 + 8 * NPIX;
            if (full) {
                *(float2*)p0 = make_float2(acc[mf][nf][0], acc[mf][nf][1]);
                *(float2*)p1 = make_float2(acc[mf][nf][2], acc[mf][nf][3]);
            } else {
                if (c < NPIX)     { p0[0] = acc[mf][nf][0]; p1[0] = acc[mf][nf][2]; }
                if (c + 1 < NPIX) { p0[1] = acc[mf][nf][1]; p1[1] = acc[mf][nf][3]; }
            }
        }
    }
}

extern "C" void kernel_launch(void* const* d_in, const int* in_sizes, int n_in,
                              void* d_out, int out_size)
{
    const float* X  = (const float*)d_in[0];   // (128, 224, 224) fp32
    const float* Wt = (const float*)d_in[1];   // (256, 128, 3, 3) fp32
    float* O        = (float*)d_out;           // (256, 222, 222) fp32

    cudaFuncSetAttribute(conv_mma2_kernel,
                         cudaFuncAttributeMaxDynamicSharedMemorySize, SMEM_TOTAL);

    dim3 grid((NPIX + BN - 1) / BN, COUT / BM);   // 193 x 2 = 386 CTAs
    conv_mma2_kernel<<<grid, NTH, SMEM_TOTAL>>>(X, Wt, O);
}